// round 15
// baseline (speedup 1.0000x reference)
#include <cuda_runtime.h>
#include <cuda_fp16.h>
#include <cstdint>
#include <math.h>

#define BB   4
#define SS   2048
#define EE   1024
#define HH   16
#define DKK  64
#define MTOT (BB*SS)   // 8192

// Scratch (device globals; no allocation allowed) — all fp16.
__device__ __half g_X[(size_t)MTOT*EE];
__device__ __half g_Q[(size_t)BB*HH*SS*DKK];
__device__ __half g_K[(size_t)BB*HH*SS*DKK];
__device__ __half g_V[(size_t)BB*HH*SS*DKK];
__device__ __half g_A[(size_t)MTOT*EE];
__device__ __half g_WT[(size_t)4*EE*EE];          // transposed [n][k] weights

// ===========================================================================
// helpers
// ===========================================================================

__device__ __forceinline__ void mma_f16(float* c, const uint32_t* a,
                                        uint32_t b0, uint32_t b1) {
    asm volatile(
        "mma.sync.aligned.m16n8k16.row.col.f32.f16.f16.f32 "
        "{%0,%1,%2,%3}, {%4,%5,%6,%7}, {%8,%9}, {%0,%1,%2,%3};"
        : "+f"(c[0]), "+f"(c[1]), "+f"(c[2]), "+f"(c[3])
        : "r"(a[0]), "r"(a[1]), "r"(a[2]), "r"(a[3]), "r"(b0), "r"(b1));
}

__device__ __forceinline__ void ldsm_x4(uint32_t* r, uint32_t addr) {
    asm volatile("ldmatrix.sync.aligned.m8n8.x4.shared.b16 {%0,%1,%2,%3}, [%4];"
                 : "=r"(r[0]), "=r"(r[1]), "=r"(r[2]), "=r"(r[3]) : "r"(addr));
}
__device__ __forceinline__ void ldsm_x4_t(uint32_t* r, uint32_t addr) {
    asm volatile("ldmatrix.sync.aligned.m8n8.x4.trans.shared.b16 {%0,%1,%2,%3}, [%4];"
                 : "=r"(r[0]), "=r"(r[1]), "=r"(r[2]), "=r"(r[3]) : "r"(addr));
}

__device__ __forceinline__ uint32_t smem_u32(const void* p) {
    uint32_t a;
    asm("{ .reg .u64 t; cvta.to.shared.u64 t, %1; cvt.u32.u64 %0, t; }"
        : "=r"(a) : "l"(p));
    return a;
}

__device__ __forceinline__ float ex2f(float v) {
    float r;
    asm("ex2.approx.f32 %0, %1;" : "=f"(r) : "f"(v));
    return r;
}

__device__ __forceinline__ void cp16(uint32_t dst, const void* src) {
    asm volatile("cp.async.cg.shared.global [%0], [%1], 16;"
                 :: "r"(dst), "l"(src) : "memory");
}
#define CP_COMMIT() asm volatile("cp.async.commit_group;" ::: "memory")
#define CP_WAIT(N)  asm volatile("cp.async.wait_group %0;" :: "n"(N) : "memory")

// exp(s/8) = exp2(s * C2)
#define C2EXP 0.18033688011112042f

// ===========================================================================
// Prepass: round X to fp16.
// ===========================================================================
__global__ __launch_bounds__(256) void xround_kernel(const float* __restrict__ X)
{
    size_t i = ((size_t)blockIdx.x * 256 + threadIdx.x) * 4;
    float4 v = *(const float4*)(X + i);
    __half2* o = (__half2*)(g_X + i);
    o[0] = __floats2half2_rn(v.x, v.y);
    o[1] = __floats2half2_rn(v.z, v.w);
}

// Weight transpose + round: g_WT[w][n][k] = h(W_w[k][n])
__global__ __launch_bounds__(256) void wtrans_kernel(
    const float* __restrict__ WQ, const float* __restrict__ WK,
    const float* __restrict__ WV, const float* __restrict__ WO)
{
    __shared__ float t[32][33];
    const int w = blockIdx.z;
    const float* W = (w == 0) ? WQ : (w == 1) ? WK : (w == 2) ? WV : WO;
    __half* O = g_WT + (size_t)w * EE * EE;
    const int n0 = blockIdx.x * 32;
    const int k0 = blockIdx.y * 32;
    const int tx = threadIdx.x, ty = threadIdx.y;

#pragma unroll
    for (int i = ty; i < 32; i += 8)
        t[i][tx] = W[(size_t)(k0 + i) * EE + n0 + tx];
    __syncthreads();
#pragma unroll
    for (int i = ty; i < 32; i += 8)
        O[(size_t)(n0 + i) * EE + k0 + tx] = __float2half_rn(t[tx][i]);
}

// ===========================================================================
// fp16 GEMM v4: 256m x 128n tile, 256 thr (8 warps, each 64m x 64n).
// K-chunk 64, 3-stage cp.async ring, ONE sync per chunk, 16 chunks.
// ldsm/mma = 8/32 per k-step (was 6/16) -> L1 wavefronts halve per MMA.
// Stage: A[256][72h] (36864 B) + B[128][72h] (18432 B) = 55296 B; x3 = 166KB.
// ===========================================================================
#define GSTAGE 55296u
#define GA_B   36864u
#define GEMM_SMEM_BYTES (3 * GSTAGE)        // 165888

template <int MODE>
__global__ __launch_bounds__(256, 1) void gemm_tc(float* __restrict__ OutP)
{
    extern __shared__ char smem[];
    const uint32_t sb = smem_u32(smem);
    const int tid  = threadIdx.x;
    const int lane = tid & 31;
    const int w    = tid >> 5;
    const int g    = lane >> 2;
    const int tg   = lane & 3;
    const int wm   = w & 3;                 // 4 warps along m, 64 rows each
    const int wn   = w >> 2;                // 2 warps along n, 64 cols each
    const int m0   = blockIdx.y * 256;
    const int n0   = blockIdx.x * 128;

    const __half* Ag = MODE ? g_A : g_X;
    const __half* Bt = g_WT + (size_t)(MODE ? 3 : blockIdx.z) * EE * EE;
    __half* outh = nullptr;
    if (!MODE) outh = (blockIdx.z == 0) ? g_Q : (blockIdx.z == 1) ? g_K : g_V;

    const uint32_t off = (uint32_t)(lane & 15) * 144u + ((lane >> 4) & 1) * 16u;

    auto issue = [&](int s) {
        const uint32_t ab = sb + (uint32_t)(s % 3) * GSTAGE;
        const uint32_t bb = ab + GA_B;
        const int k0 = s * 64;
#pragma unroll
        for (int i = 0; i < 8; i++) {        // A: 256 rows x 8 segs
            int f = tid + i * 256;
            int r = f >> 3, c = f & 7;
            cp16(ab + (uint32_t)r * 144u + c * 16u,
                 Ag + (size_t)(m0 + r) * EE + k0 + c * 8);
        }
#pragma unroll
        for (int i = 0; i < 4; i++) {        // B: 128 rows x 8 segs
            int f = tid + i * 256;
            int r = f >> 3, c = f & 7;
            cp16(bb + (uint32_t)r * 144u + c * 16u,
                 Bt + (size_t)(n0 + r) * EE + k0 + c * 8);
        }
    };

    float c[4][8][4];
#pragma unroll
    for (int mt = 0; mt < 4; mt++)
#pragma unroll
        for (int nt = 0; nt < 8; nt++)
#pragma unroll
            for (int i = 0; i < 4; i++) c[mt][nt][i] = 0.f;

    issue(0); CP_COMMIT();
    issue(1); CP_COMMIT();

    for (int j = 0; j < 16; j++) {
        CP_WAIT(1);                      // stage j landed
        __syncthreads();                 // publish j; all done with j-1
        if (j + 2 < 16) issue(j + 2);    // slot (j+2)%3 (held j-1, retired)
        CP_COMMIT();

        const uint32_t ab = sb + (uint32_t)(j % 3) * GSTAGE;
        const uint32_t bb = ab + GA_B;
#pragma unroll
        for (int ks = 0; ks < 4; ks++) {
            uint32_t a[4][4], bq[4][4];
#pragma unroll
            for (int mt = 0; mt < 4; mt++)
                ldsm_x4(a[mt], ab + (uint32_t)(wm * 64 + mt * 16) * 144u + ks * 32u + off);
#pragma unroll
            for (int p = 0; p < 4; p++)
                ldsm_x4(bq[p], bb + (uint32_t)(wn * 64 + p * 16) * 144u + ks * 32u + off);
#pragma unroll
            for (int mt = 0; mt < 4; mt++)
#pragma unroll
                for (int nt = 0; nt < 8; nt++)
                    mma_f16(c[mt][nt], a[mt],
                            bq[nt >> 1][nt & 1], bq[nt >> 1][(nt & 1) + 2]);
        }
    }

#pragma unroll
    for (int mt = 0; mt < 4; mt++) {
#pragma unroll
        for (int nt = 0; nt < 8; nt++) {
            int row = m0 + wm * 64 + mt * 16 + g;
            int col = n0 + wn * 64 + nt * 8 + 2 * tg;
            if (MODE) {
                float* o0 = OutP + (size_t)row * EE + col;
                float* o1 = OutP + (size_t)(row + 8) * EE + col;
                *(float2*)o0 = make_float2(c[mt][nt][0], c[mt][nt][1]);
                *(float2*)o1 = make_float2(c[mt][nt][2], c[mt][nt][3]);
            } else {
                int bidx = row >> 11;
                int s    = row & (SS - 1);
                int h    = col >> 6;
                int d    = col & 63;
                __half* o0 = outh + (((size_t)(bidx * HH + h) * SS + s    ) * DKK + d);
                __half* o1 = outh + (((size_t)(bidx * HH + h) * SS + s + 8) * DKK + d);
                *(__half2*)o0 = __floats2half2_rn(c[mt][nt][0], c[mt][nt][1]);
                *(__half2*)o1 = __floats2half2_rn(c[mt][nt][2], c[mt][nt][3]);
            }
        }
    }
}

// ===========================================================================
// Causal flash attention (unchanged from R14): 128 q-rows, 4 warps,
// 2-stage KV ring, 3 CTAs/SM, raw-domain ex2 softmax.
// ===========================================================================
#define ATB 144u
#define AQROWS 128
#define OFF_KV 18432u
#define KVSTG  18432u
#define OFF_P  (18432u + 2u * KVSTG)      // 55296
#define ATTN_SMEM_BYTES 73728

__global__ __launch_bounds__(128, 3) void attn_tc()
{
    extern __shared__ char smem[];
    const uint32_t sb = smem_u32(smem);

    const int tid  = threadIdx.x;
    const int lane = tid & 31;
    const int w    = tid >> 5;               // 0..3
    const int g    = lane >> 2;
    const int tg   = lane & 3;

    const int qblk = gridDim.x - 1 - blockIdx.x;   // heavy CTAs first
    const int q0   = qblk * AQROWS;
    const int h    = blockIdx.y;
    const int b    = blockIdx.z;
    const size_t base = ((size_t)(b * HH + h) * SS) * DKK;

    const uint32_t off = (uint32_t)(lane & 15) * ATB + ((lane >> 4) & 1) * 16u;

    auto issue_KV = [&](int j) {
        const uint32_t kd = sb + OFF_KV + (uint32_t)(j & 1) * KVSTG;
        const uint32_t vd = kd + 9216u;
        const int t0 = j * 64;
#pragma unroll
        for (int i = 0; i < 4; i++) {
            int f = tid + i * 128;
            int r = f >> 3, c = f & 7;
            cp16(kd + (uint32_t)r * ATB + c * 16u,
                 g_K + base + (size_t)(t0 + r) * DKK + c * 8);
            cp16(vd + (uint32_t)r * ATB + c * 16u,
                 g_V + base + (size_t)(t0 + r) * DKK + c * 8);
        }
    };

    const int nch = 2 * qblk + 2;
    issue_KV(0); CP_COMMIT();
    if (nch > 1) issue_KV(1);
    CP_COMMIT();

    // Stage Q (half, pre-rounded), 128x64.
#pragma unroll
    for (int i = 0; i < 8; i++) {
        int f = tid + i * 128;
        int r = f >> 3, c = f & 7;
        uint4 v = *(const uint4*)(g_Q + base + (size_t)(q0 + r) * DKK + c * 8);
        *(uint4*)(smem + (size_t)r * ATB + c * 16) = v;
    }

    float o[2][8][4];
#pragma unroll
    for (int mt = 0; mt < 2; mt++)
#pragma unroll
        for (int nt = 0; nt < 8; nt++)
#pragma unroll
            for (int i = 0; i < 4; i++) o[mt][nt][i] = 0.f;
    float mrow[2][2], lrow[2][2];
#pragma unroll
    for (int mt = 0; mt < 2; mt++) {
        mrow[mt][0] = -1e30f; mrow[mt][1] = -1e30f;
        lrow[mt][0] = 0.f;    lrow[mt][1] = 0.f;
    }

    const int rbase = w * 32;

    for (int j = 0; j < nch; j++) {
        CP_WAIT(1);                      // KV stage j landed
        __syncthreads();                 // publish stage j

        const uint32_t kdb = sb + OFF_KV + (uint32_t)(j & 1) * KVSTG;
        const uint32_t vdb = kdb + 9216u;
        const int t0 = j * 64;
        const bool active = (t0 <= q0 + rbase + 31);
        const bool diag   = (t0 + 63 > q0 + rbase);

        if (active) {
            // ---- S = Q K^T (raw scores) ----
            float s[2][8][4];
#pragma unroll
            for (int mt = 0; mt < 2; mt++)
#pragma unroll
                for (int nt = 0; nt < 8; nt++)
#pragma unroll
                    for (int i = 0; i < 4; i++) s[mt][nt][i] = 0.f;

#pragma unroll
            for (int ks = 0; ks < 4; ks++) {
                uint32_t a[2][4], bq[4][4];
                ldsm_x4(a[0], sb + (uint32_t)(rbase     ) * ATB + ks * 32u + off);
                ldsm_x4(a[1], sb + (uint32_t)(rbase + 16) * ATB + ks * 32u + off);
#pragma unroll
                for (int p = 0; p < 4; p++)
                    ldsm_x4(bq[p], kdb + (uint32_t)(p * 16) * ATB + ks * 32u + off);
#pragma unroll
                for (int mt = 0; mt < 2; mt++)
#pragma unroll
                    for (int nt = 0; nt < 8; nt++)
                        mma_f16(s[mt][nt], a[mt],
                                bq[nt >> 1][nt & 1], bq[nt >> 1][(nt & 1) + 2]);
            }

            // ---- causal mask (diag chunks only) ----
            if (diag) {
#pragma unroll
                for (int mt = 0; mt < 2; mt++) {
                    const int grow0 = q0 + rbase + mt * 16 + g;
#pragma unroll
                    for (int nt = 0; nt < 8; nt++) {
                        int c0 = t0 + nt * 8 + 2 * tg;
                        int c1 = c0 + 1;
                        if (c0 > grow0    ) s[mt][nt][0] = -1e30f;
                        if (c1 > grow0    ) s[mt][nt][1] = -1e30f;
                        if (c0 > grow0 + 8) s[mt][nt][2] = -1e30f;
                        if (c1 > grow0 + 8) s[mt][nt][3] = -1e30f;
                    }
                }
            }

            // ---- online softmax, raw domain, ex2 ----
#pragma unroll
            for (int mt = 0; mt < 2; mt++) {
                float mx0 = -1e30f, mx1 = -1e30f;
#pragma unroll
                for (int nt = 0; nt < 8; nt++) {
                    mx0 = fmaxf(mx0, fmaxf(s[mt][nt][0], s[mt][nt][1]));
                    mx1 = fmaxf(mx1, fmaxf(s[mt][nt][2], s[mt][nt][3]));
                }
                mx0 = fmaxf(mx0, __shfl_xor_sync(0xffffffffu, mx0, 1));
                mx0 = fmaxf(mx0, __shfl_xor_sync(0xffffffffu, mx0, 2));
                mx1 = fmaxf(mx1, __shfl_xor_sync(0xffffffffu, mx1, 1));
                mx1 = fmaxf(mx1, __shfl_xor_sync(0xffffffffu, mx1, 2));
                float mn0 = fmaxf(mrow[mt][0], mx0), mn1 = fmaxf(mrow[mt][1], mx1);
                float sc0 = ex2f((mrow[mt][0] - mn0) * C2EXP);
                float sc1 = ex2f((mrow[mt][1] - mn1) * C2EXP);
                const float b0 = -mn0 * C2EXP;
                const float b1 = -mn1 * C2EXP;

                float rs0 = 0.f, rs1 = 0.f;
#pragma unroll
                for (int nt = 0; nt < 8; nt++) {
                    __half2 h01 = __floats2half2_rn(ex2f(fmaf(s[mt][nt][0], C2EXP, b0)),
                                                    ex2f(fmaf(s[mt][nt][1], C2EXP, b0)));
                    __half2 h23 = __floats2half2_rn(ex2f(fmaf(s[mt][nt][2], C2EXP, b1)),
                                                    ex2f(fmaf(s[mt][nt][3], C2EXP, b1)));
                    float2 f01 = __half22float2(h01);
                    float2 f23 = __half22float2(h23);
                    rs0 += f01.x + f01.y;
                    rs1 += f23.x + f23.y;
                    *(__half2*)(smem + OFF_P +
                        (size_t)(rbase + mt * 16 + g    ) * ATB + (nt * 8 + 2 * tg) * 2) = h01;
                    *(__half2*)(smem + OFF_P +
                        (size_t)(rbase + mt * 16 + g + 8) * ATB + (nt * 8 + 2 * tg) * 2) = h23;
                }
                rs0 += __shfl_xor_sync(0xffffffffu, rs0, 1);
                rs0 += __shfl_xor_sync(0xffffffffu, rs0, 2);
                rs1 += __shfl_xor_sync(0xffffffffu, rs1, 1);
                rs1 += __shfl_xor_sync(0xffffffffu, rs1, 2);
                lrow[mt][0] = lrow[mt][0] * sc0 + rs0;
                lrow[mt][1] = lrow[mt][1] * sc1 + rs1;
                mrow[mt][0] = mn0; mrow[mt][1] = mn1;
#pragma unroll
                for (int nt = 0; nt < 8; nt++) {
                    o[mt][nt][0] *= sc0; o[mt][nt][1] *= sc0;
                    o[mt][nt][2] *= sc1; o[mt][nt][3] *= sc1;
                }
            }
            __syncwarp();                 // P visible to whole warp

            // ---- O += P V (B via ldmatrix.trans on V [t][d]) ----
#pragma unroll
            for (int ks = 0; ks < 4; ks++) {
                uint32_t a[2][4], bv[4][4];
                ldsm_x4(a[0], sb + OFF_P + (uint32_t)(rbase     ) * ATB + ks * 32u + off);
                ldsm_x4(a[1], sb + OFF_P + (uint32_t)(rbase + 16) * ATB + ks * 32u + off);
#pragma unroll
                for (int p = 0; p < 4; p++)
                    ldsm_x4_t(bv[p], vdb + (uint32_t)(ks * 16) * ATB + p * 32u + off);
#pragma unroll
                for (int mt = 0; mt < 2; mt++)
#pragma unroll
                    for (int nt = 0; nt < 8; nt++)
                        mma_f16(o[mt][nt], a[mt],
                                bv[nt >> 1][(nt & 1) * 2], bv[nt >> 1][(nt & 1) * 2 + 1]);
            }
        }

        __syncthreads();                 // all warps done with stage j
        if (j + 2 < nch) issue_KV(j + 2);   // refill slot j&1
        CP_COMMIT();
    }

    // Epilogue: normalize, round, write g_A (half) [B,S,E].
#pragma unroll
    for (int mt = 0; mt < 2; mt++) {
        const float inv0 = 1.0f / lrow[mt][0];
        const float inv1 = 1.0f / lrow[mt][1];
        const int row0 = q0 + rbase + mt * 16 + g;
#pragma unroll
        for (int nt = 0; nt < 8; nt++) {
            int d = nt * 8 + 2 * tg;
            __half* p0 = g_A + ((size_t)b * SS + row0    ) * EE + h * DKK + d;
            __half* p1 = g_A + ((size_t)b * SS + row0 + 8) * EE + h * DKK + d;
            *(__half2*)p0 = __floats2half2_rn(o[mt][nt][0] * inv0, o[mt][nt][1] * inv0);
            *(__half2*)p1 = __floats2half2_rn(o[mt][nt][2] * inv1, o[mt][nt][3] * inv1);
        }
    }
}

// ===========================================================================

extern "C" void kernel_launch(void* const* d_in, const int* in_sizes, int n_in,
                              void* d_out, int out_size)
{
    const float* x  = (const float*)d_in[0];
    const float* WQ = (const float*)d_in[1];
    const float* WK = (const float*)d_in[2];
    const float* WV = (const float*)d_in[3];
    const float* WO = (const float*)d_in[4];
    float* out = (float*)d_out;

    (void)in_sizes; (void)n_in; (void)out_size;

    // 0) Round X to fp16; transpose+round weights.
    xround_kernel<<<(MTOT * EE) / (256 * 4), 256>>>(x);
    wtrans_kernel<<<dim3(EE / 32, EE / 32, 4), dim3(32, 8)>>>(WQ, WK, WV, WO);

    // 1) QKV projections (fp16 mma, 256x128 tiles).
    cudaFuncSetAttribute(gemm_tc<0>,
                         cudaFuncAttributeMaxDynamicSharedMemorySize,
                         GEMM_SMEM_BYTES);
    gemm_tc<0><<<dim3(EE / 128, MTOT / 256, 3), 256, GEMM_SMEM_BYTES>>>(nullptr);

    // 2) Causal flash attention (128 q-rows/CTA, 3 CTAs per SM).
    cudaFuncSetAttribute(attn_tc,
                         cudaFuncAttributeMaxDynamicSharedMemorySize,
                         ATTN_SMEM_BYTES);
    attn_tc<<<dim3(SS / AQROWS, HH, BB), 128, ATTN_SMEM_BYTES>>>();

    // 3) Output projection (fp16 mma, f32 out).
    cudaFuncSetAttribute(gemm_tc<1>,
                         cudaFuncAttributeMaxDynamicSharedMemorySize,
                         GEMM_SMEM_BYTES);
    gemm_tc<1><<<dim3(EE / 128, MTOT / 256), 256, GEMM_SMEM_BYTES>>>(out);
}

// round 16
// speedup vs baseline: 1.0501x; 1.0501x over previous
#include <cuda_runtime.h>
#include <cuda_fp16.h>
#include <cstdint>
#include <math.h>

#define BB   4
#define SS   2048
#define EE   1024
#define HH   16
#define DKK  64
#define MTOT (BB*SS)   // 8192

// Scratch (device globals; no allocation allowed) — all fp16.
__device__ __half g_X[(size_t)MTOT*EE];
__device__ __half g_Q[(size_t)BB*HH*SS*DKK];
__device__ __half g_K[(size_t)BB*HH*SS*DKK];
__device__ __half g_V[(size_t)BB*HH*SS*DKK];
__device__ __half g_A[(size_t)MTOT*EE];
__device__ __half g_WT[(size_t)4*EE*EE];          // transposed [n][k] weights

// ===========================================================================
// helpers
// ===========================================================================

__device__ __forceinline__ void mma_f16(float* c, const uint32_t* a,
                                        uint32_t b0, uint32_t b1) {
    asm volatile(
        "mma.sync.aligned.m16n8k16.row.col.f32.f16.f16.f32 "
        "{%0,%1,%2,%3}, {%4,%5,%6,%7}, {%8,%9}, {%0,%1,%2,%3};"
        : "+f"(c[0]), "+f"(c[1]), "+f"(c[2]), "+f"(c[3])
        : "r"(a[0]), "r"(a[1]), "r"(a[2]), "r"(a[3]), "r"(b0), "r"(b1));
}

__device__ __forceinline__ void ldsm_x4(uint32_t* r, uint32_t addr) {
    asm volatile("ldmatrix.sync.aligned.m8n8.x4.shared.b16 {%0,%1,%2,%3}, [%4];"
                 : "=r"(r[0]), "=r"(r[1]), "=r"(r[2]), "=r"(r[3]) : "r"(addr));
}
__device__ __forceinline__ void ldsm_x4_t(uint32_t* r, uint32_t addr) {
    asm volatile("ldmatrix.sync.aligned.m8n8.x4.trans.shared.b16 {%0,%1,%2,%3}, [%4];"
                 : "=r"(r[0]), "=r"(r[1]), "=r"(r[2]), "=r"(r[3]) : "r"(addr));
}

__device__ __forceinline__ uint32_t smem_u32(const void* p) {
    uint32_t a;
    asm("{ .reg .u64 t; cvta.to.shared.u64 t, %1; cvt.u32.u64 %0, t; }"
        : "=r"(a) : "l"(p));
    return a;
}

__device__ __forceinline__ float ex2f(float v) {
    float r;
    asm("ex2.approx.f32 %0, %1;" : "=f"(r) : "f"(v));
    return r;
}

__device__ __forceinline__ void cp16(uint32_t dst, const void* src) {
    asm volatile("cp.async.cg.shared.global [%0], [%1], 16;"
                 :: "r"(dst), "l"(src) : "memory");
}
#define CP_COMMIT() asm volatile("cp.async.commit_group;" ::: "memory")
#define CP_WAIT(N)  asm volatile("cp.async.wait_group %0;" :: "n"(N) : "memory")

// exp(s/8) = exp2(s * C2)
#define C2EXP 0.18033688011112042f

// ===========================================================================
// Prepass: round X to fp16.
// ===========================================================================
__global__ __launch_bounds__(256) void xround_kernel(const float* __restrict__ X)
{
    size_t i = ((size_t)blockIdx.x * 256 + threadIdx.x) * 4;
    float4 v = *(const float4*)(X + i);
    __half2* o = (__half2*)(g_X + i);
    o[0] = __floats2half2_rn(v.x, v.y);
    o[1] = __floats2half2_rn(v.z, v.w);
}

// Weight transpose + round: g_WT[w][n][k] = h(W_w[k][n])
__global__ __launch_bounds__(256) void wtrans_kernel(
    const float* __restrict__ WQ, const float* __restrict__ WK,
    const float* __restrict__ WV, const float* __restrict__ WO)
{
    __shared__ float t[32][33];
    const int w = blockIdx.z;
    const float* W = (w == 0) ? WQ : (w == 1) ? WK : (w == 2) ? WV : WO;
    __half* O = g_WT + (size_t)w * EE * EE;
    const int n0 = blockIdx.x * 32;
    const int k0 = blockIdx.y * 32;
    const int tx = threadIdx.x, ty = threadIdx.y;

#pragma unroll
    for (int i = ty; i < 32; i += 8)
        t[i][tx] = W[(size_t)(k0 + i) * EE + n0 + tx];
    __syncthreads();
#pragma unroll
    for (int i = ty; i < 32; i += 8)
        O[(size_t)(n0 + i) * EE + k0 + tx] = __float2half_rn(t[tx][i]);
}

// ===========================================================================
// fp16 GEMM v5: 128x128 tile, 128 thr (4 warps, each 64m x 64n).
// K-chunk 64, 3-stage cp.async ring, ONE sync per chunk, 16 chunks.
// Per k-step per warp: 8 ldsm for 32 MMAs (ldsm/mma = 0.25).
// Stage: A[128][72h] + B[128][72h] = 36864 B; x3 = 110592 B -> 2 CTAs/SM.
// At 2x128 thr/SM, reg budget = 256/thread: 128 accum regs fit w/o spills.
// ===========================================================================
#define GSTAGE 36864u
#define GEMM_SMEM_BYTES (3 * GSTAGE)        // 110592

template <int MODE>
__global__ __launch_bounds__(128, 2) void gemm_tc(float* __restrict__ OutP)
{
    extern __shared__ char smem[];
    const uint32_t sb = smem_u32(smem);
    const int tid  = threadIdx.x;
    const int lane = tid & 31;
    const int w    = tid >> 5;              // 0..3
    const int g    = lane >> 2;
    const int tg   = lane & 3;
    const int wm   = w & 1;                 // 2 warps along m, 64 rows each
    const int wn   = w >> 1;                // 2 warps along n, 64 cols each
    const int m0   = blockIdx.y * 128;
    const int n0   = blockIdx.x * 128;

    const __half* Ag = MODE ? g_A : g_X;
    const __half* Bt = g_WT + (size_t)(MODE ? 3 : blockIdx.z) * EE * EE;
    __half* outh = nullptr;
    if (!MODE) outh = (blockIdx.z == 0) ? g_Q : (blockIdx.z == 1) ? g_K : g_V;

    const uint32_t off = (uint32_t)(lane & 15) * 144u + ((lane >> 4) & 1) * 16u;

    auto issue = [&](int s) {
        const uint32_t ab = sb + (uint32_t)(s % 3) * GSTAGE;
        const uint32_t bb = ab + 18432u;
        const int k0 = s * 64;
#pragma unroll
        for (int i = 0; i < 8; i++) {        // A: 128 rows x 8 segs, 128 thr
            int f = tid + i * 128;
            int r = f >> 3, c = f & 7;
            cp16(ab + (uint32_t)r * 144u + c * 16u,
                 Ag + (size_t)(m0 + r) * EE + k0 + c * 8);
        }
#pragma unroll
        for (int i = 0; i < 8; i++) {        // B: 128 rows x 8 segs
            int f = tid + i * 128;
            int r = f >> 3, c = f & 7;
            cp16(bb + (uint32_t)r * 144u + c * 16u,
                 Bt + (size_t)(n0 + r) * EE + k0 + c * 8);
        }
    };

    float c[4][8][4];
#pragma unroll
    for (int mt = 0; mt < 4; mt++)
#pragma unroll
        for (int nt = 0; nt < 8; nt++)
#pragma unroll
            for (int i = 0; i < 4; i++) c[mt][nt][i] = 0.f;

    issue(0); CP_COMMIT();
    issue(1); CP_COMMIT();

    for (int j = 0; j < 16; j++) {
        CP_WAIT(1);                      // stage j landed
        __syncthreads();                 // publish j; all done with j-1
        if (j + 2 < 16) issue(j + 2);    // slot (j+2)%3 (held j-1, retired)
        CP_COMMIT();

        const uint32_t ab = sb + (uint32_t)(j % 3) * GSTAGE;
        const uint32_t bb = ab + 18432u;
#pragma unroll
        for (int ks = 0; ks < 4; ks++) {
            uint32_t a[4][4], bq[4][4];
#pragma unroll
            for (int mt = 0; mt < 4; mt++)
                ldsm_x4(a[mt], ab + (uint32_t)(wm * 64 + mt * 16) * 144u + ks * 32u + off);
#pragma unroll
            for (int p = 0; p < 4; p++)
                ldsm_x4(bq[p], bb + (uint32_t)(wn * 64 + p * 16) * 144u + ks * 32u + off);
#pragma unroll
            for (int mt = 0; mt < 4; mt++)
#pragma unroll
                for (int nt = 0; nt < 8; nt++)
                    mma_f16(c[mt][nt], a[mt],
                            bq[nt >> 1][nt & 1], bq[nt >> 1][(nt & 1) + 2]);
        }
    }

#pragma unroll
    for (int mt = 0; mt < 4; mt++) {
#pragma unroll
        for (int nt = 0; nt < 8; nt++) {
            int row = m0 + wm * 64 + mt * 16 + g;
            int col = n0 + wn * 64 + nt * 8 + 2 * tg;
            if (MODE) {
                float* o0 = OutP + (size_t)row * EE + col;
                float* o1 = OutP + (size_t)(row + 8) * EE + col;
                *(float2*)o0 = make_float2(c[mt][nt][0], c[mt][nt][1]);
                *(float2*)o1 = make_float2(c[mt][nt][2], c[mt][nt][3]);
            } else {
                int bidx = row >> 11;
                int s    = row & (SS - 1);
                int h    = col >> 6;
                int d    = col & 63;
                __half* o0 = outh + (((size_t)(bidx * HH + h) * SS + s    ) * DKK + d);
                __half* o1 = outh + (((size_t)(bidx * HH + h) * SS + s + 8) * DKK + d);
                *(__half2*)o0 = __floats2half2_rn(c[mt][nt][0], c[mt][nt][1]);
                *(__half2*)o1 = __floats2half2_rn(c[mt][nt][2], c[mt][nt][3]);
            }
        }
    }
}

// ===========================================================================
// Causal flash attention (unchanged from R14): 128 q-rows, 4 warps,
// 2-stage KV ring, 3 CTAs/SM, raw-domain ex2 softmax.
// ===========================================================================
#define ATB 144u
#define AQROWS 128
#define OFF_KV 18432u
#define KVSTG  18432u
#define OFF_P  (18432u + 2u * KVSTG)      // 55296
#define ATTN_SMEM_BYTES 73728

__global__ __launch_bounds__(128, 3) void attn_tc()
{
    extern __shared__ char smem[];
    const uint32_t sb = smem_u32(smem);

    const int tid  = threadIdx.x;
    const int lane = tid & 31;
    const int w    = tid >> 5;               // 0..3
    const int g    = lane >> 2;
    const int tg   = lane & 3;

    const int qblk = gridDim.x - 1 - blockIdx.x;   // heavy CTAs first
    const int q0   = qblk * AQROWS;
    const int h    = blockIdx.y;
    const int b    = blockIdx.z;
    const size_t base = ((size_t)(b * HH + h) * SS) * DKK;

    const uint32_t off = (uint32_t)(lane & 15) * ATB + ((lane >> 4) & 1) * 16u;

    auto issue_KV = [&](int j) {
        const uint32_t kd = sb + OFF_KV + (uint32_t)(j & 1) * KVSTG;
        const uint32_t vd = kd + 9216u;
        const int t0 = j * 64;
#pragma unroll
        for (int i = 0; i < 4; i++) {
            int f = tid + i * 128;
            int r = f >> 3, c = f & 7;
            cp16(kd + (uint32_t)r * ATB + c * 16u,
                 g_K + base + (size_t)(t0 + r) * DKK + c * 8);
            cp16(vd + (uint32_t)r * ATB + c * 16u,
                 g_V + base + (size_t)(t0 + r) * DKK + c * 8);
        }
    };

    const int nch = 2 * qblk + 2;
    issue_KV(0); CP_COMMIT();
    if (nch > 1) issue_KV(1);
    CP_COMMIT();

    // Stage Q (half, pre-rounded), 128x64.
#pragma unroll
    for (int i = 0; i < 8; i++) {
        int f = tid + i * 128;
        int r = f >> 3, c = f & 7;
        uint4 v = *(const uint4*)(g_Q + base + (size_t)(q0 + r) * DKK + c * 8);
        *(uint4*)(smem + (size_t)r * ATB + c * 16) = v;
    }

    float o[2][8][4];
#pragma unroll
    for (int mt = 0; mt < 2; mt++)
#pragma unroll
        for (int nt = 0; nt < 8; nt++)
#pragma unroll
            for (int i = 0; i < 4; i++) o[mt][nt][i] = 0.f;
    float mrow[2][2], lrow[2][2];
#pragma unroll
    for (int mt = 0; mt < 2; mt++) {
        mrow[mt][0] = -1e30f; mrow[mt][1] = -1e30f;
        lrow[mt][0] = 0.f;    lrow[mt][1] = 0.f;
    }

    const int rbase = w * 32;

    for (int j = 0; j < nch; j++) {
        CP_WAIT(1);                      // KV stage j landed
        __syncthreads();                 // publish stage j

        const uint32_t kdb = sb + OFF_KV + (uint32_t)(j & 1) * KVSTG;
        const uint32_t vdb = kdb + 9216u;
        const int t0 = j * 64;
        const bool active = (t0 <= q0 + rbase + 31);
        const bool diag   = (t0 + 63 > q0 + rbase);

        if (active) {
            // ---- S = Q K^T (raw scores) ----
            float s[2][8][4];
#pragma unroll
            for (int mt = 0; mt < 2; mt++)
#pragma unroll
                for (int nt = 0; nt < 8; nt++)
#pragma unroll
                    for (int i = 0; i < 4; i++) s[mt][nt][i] = 0.f;

#pragma unroll
            for (int ks = 0; ks < 4; ks++) {
                uint32_t a[2][4], bq[4][4];
                ldsm_x4(a[0], sb + (uint32_t)(rbase     ) * ATB + ks * 32u + off);
                ldsm_x4(a[1], sb + (uint32_t)(rbase + 16) * ATB + ks * 32u + off);
#pragma unroll
                for (int p = 0; p < 4; p++)
                    ldsm_x4(bq[p], kdb + (uint32_t)(p * 16) * ATB + ks * 32u + off);
#pragma unroll
                for (int mt = 0; mt < 2; mt++)
#pragma unroll
                    for (int nt = 0; nt < 8; nt++)
                        mma_f16(s[mt][nt], a[mt],
                                bq[nt >> 1][nt & 1], bq[nt >> 1][(nt & 1) + 2]);
            }

            // ---- causal mask (diag chunks only) ----
            if (diag) {
#pragma unroll
                for (int mt = 0; mt < 2; mt++) {
                    const int grow0 = q0 + rbase + mt * 16 + g;
#pragma unroll
                    for (int nt = 0; nt < 8; nt++) {
                        int c0 = t0 + nt * 8 + 2 * tg;
                        int c1 = c0 + 1;
                        if (c0 > grow0    ) s[mt][nt][0] = -1e30f;
                        if (c1 > grow0    ) s[mt][nt][1] = -1e30f;
                        if (c0 > grow0 + 8) s[mt][nt][2] = -1e30f;
                        if (c1 > grow0 + 8) s[mt][nt][3] = -1e30f;
                    }
                }
            }

            // ---- online softmax, raw domain, ex2 ----
#pragma unroll
            for (int mt = 0; mt < 2; mt++) {
                float mx0 = -1e30f, mx1 = -1e30f;
#pragma unroll
                for (int nt = 0; nt < 8; nt++) {
                    mx0 = fmaxf(mx0, fmaxf(s[mt][nt][0], s[mt][nt][1]));
                    mx1 = fmaxf(mx1, fmaxf(s[mt][nt][2], s[mt][nt][3]));
                }
                mx0 = fmaxf(mx0, __shfl_xor_sync(0xffffffffu, mx0, 1));
                mx0 = fmaxf(mx0, __shfl_xor_sync(0xffffffffu, mx0, 2));
                mx1 = fmaxf(mx1, __shfl_xor_sync(0xffffffffu, mx1, 1));
                mx1 = fmaxf(mx1, __shfl_xor_sync(0xffffffffu, mx1, 2));
                float mn0 = fmaxf(mrow[mt][0], mx0), mn1 = fmaxf(mrow[mt][1], mx1);
                float sc0 = ex2f((mrow[mt][0] - mn0) * C2EXP);
                float sc1 = ex2f((mrow[mt][1] - mn1) * C2EXP);
                const float b0 = -mn0 * C2EXP;
                const float b1 = -mn1 * C2EXP;

                float rs0 = 0.f, rs1 = 0.f;
#pragma unroll
                for (int nt = 0; nt < 8; nt++) {
                    __half2 h01 = __floats2half2_rn(ex2f(fmaf(s[mt][nt][0], C2EXP, b0)),
                                                    ex2f(fmaf(s[mt][nt][1], C2EXP, b0)));
                    __half2 h23 = __floats2half2_rn(ex2f(fmaf(s[mt][nt][2], C2EXP, b1)),
                                                    ex2f(fmaf(s[mt][nt][3], C2EXP, b1)));
                    float2 f01 = __half22float2(h01);
                    float2 f23 = __half22float2(h23);
                    rs0 += f01.x + f01.y;
                    rs1 += f23.x + f23.y;
                    *(__half2*)(smem + OFF_P +
                        (size_t)(rbase + mt * 16 + g    ) * ATB + (nt * 8 + 2 * tg) * 2) = h01;
                    *(__half2*)(smem + OFF_P +
                        (size_t)(rbase + mt * 16 + g + 8) * ATB + (nt * 8 + 2 * tg) * 2) = h23;
                }
                rs0 += __shfl_xor_sync(0xffffffffu, rs0, 1);
                rs0 += __shfl_xor_sync(0xffffffffu, rs0, 2);
                rs1 += __shfl_xor_sync(0xffffffffu, rs1, 1);
                rs1 += __shfl_xor_sync(0xffffffffu, rs1, 2);
                lrow[mt][0] = lrow[mt][0] * sc0 + rs0;
                lrow[mt][1] = lrow[mt][1] * sc1 + rs1;
                mrow[mt][0] = mn0; mrow[mt][1] = mn1;
#pragma unroll
                for (int nt = 0; nt < 8; nt++) {
                    o[mt][nt][0] *= sc0; o[mt][nt][1] *= sc0;
                    o[mt][nt][2] *= sc1; o[mt][nt][3] *= sc1;
                }
            }
            __syncwarp();                 // P visible to whole warp

            // ---- O += P V (B via ldmatrix.trans on V [t][d]) ----
#pragma unroll
            for (int ks = 0; ks < 4; ks++) {
                uint32_t a[2][4], bv[4][4];
                ldsm_x4(a[0], sb + OFF_P + (uint32_t)(rbase     ) * ATB + ks * 32u + off);
                ldsm_x4(a[1], sb + OFF_P + (uint32_t)(rbase + 16) * ATB + ks * 32u + off);
#pragma unroll
                for (int p = 0; p < 4; p++)
                    ldsm_x4_t(bv[p], vdb + (uint32_t)(ks * 16) * ATB + p * 32u + off);
#pragma unroll
                for (int mt = 0; mt < 2; mt++)
#pragma unroll
                    for (int nt = 0; nt < 8; nt++)
                        mma_f16(o[mt][nt], a[mt],
                                bv[nt >> 1][(nt & 1) * 2], bv[nt >> 1][(nt & 1) * 2 + 1]);
            }
        }

        __syncthreads();                 // all warps done with stage j
        if (j + 2 < nch) issue_KV(j + 2);   // refill slot j&1
        CP_COMMIT();
    }

    // Epilogue: normalize, round, write g_A (half) [B,S,E].
#pragma unroll
    for (int mt = 0; mt < 2; mt++) {
        const float inv0 = 1.0f / lrow[mt][0];
        const float inv1 = 1.0f / lrow[mt][1];
        const int row0 = q0 + rbase + mt * 16 + g;
#pragma unroll
        for (int nt = 0; nt < 8; nt++) {
            int d = nt * 8 + 2 * tg;
            __half* p0 = g_A + ((size_t)b * SS + row0    ) * EE + h * DKK + d;
            __half* p1 = g_A + ((size_t)b * SS + row0 + 8) * EE + h * DKK + d;
            *(__half2*)p0 = __floats2half2_rn(o[mt][nt][0] * inv0, o[mt][nt][1] * inv0);
            *(__half2*)p1 = __floats2half2_rn(o[mt][nt][2] * inv1, o[mt][nt][3] * inv1);
        }
    }
}

// ===========================================================================

extern "C" void kernel_launch(void* const* d_in, const int* in_sizes, int n_in,
                              void* d_out, int out_size)
{
    const float* x  = (const float*)d_in[0];
    const float* WQ = (const float*)d_in[1];
    const float* WK = (const float*)d_in[2];
    const float* WV = (const float*)d_in[3];
    const float* WO = (const float*)d_in[4];
    float* out = (float*)d_out;

    (void)in_sizes; (void)n_in; (void)out_size;

    // 0) Round X to fp16; transpose+round weights.
    xround_kernel<<<(MTOT * EE) / (256 * 4), 256>>>(x);
    wtrans_kernel<<<dim3(EE / 32, EE / 32, 4), dim3(32, 8)>>>(WQ, WK, WV, WO);

    // 1) QKV projections (fp16 mma, 128x128 tiles, 4 fat warps, 2 CTAs/SM).
    cudaFuncSetAttribute(gemm_tc<0>,
                         cudaFuncAttributeMaxDynamicSharedMemorySize,
                         GEMM_SMEM_BYTES);
    gemm_tc<0><<<dim3(EE / 128, MTOT / 128, 3), 128, GEMM_SMEM_BYTES>>>(nullptr);

    // 2) Causal flash attention (128 q-rows/CTA, 3 CTAs per SM).
    cudaFuncSetAttribute(attn_tc,
                         cudaFuncAttributeMaxDynamicSharedMemorySize,
                         ATTN_SMEM_BYTES);
    attn_tc<<<dim3(SS / AQROWS, HH, BB), 128, ATTN_SMEM_BYTES>>>();

    // 3) Output projection (fp16 mma, f32 out).
    cudaFuncSetAttribute(gemm_tc<1>,
                         cudaFuncAttributeMaxDynamicSharedMemorySize,
                         GEMM_SMEM_BYTES);
    gemm_tc<1><<<dim3(EE / 128, MTOT / 128), 128, GEMM_SMEM_BYTES>>>(out);
}